// round 4
// baseline (speedup 1.0000x reference)
#include <cuda_runtime.h>
#include <cstdint>

#define N_ACT   1500000
#define ROWS_PB 128                            // 8 warps x 16 rows
#define NB_CONV ((N_ACT + ROWS_PB - 1) / ROWS_PB)   // 11719 blocks
#define NB_ELT  ((N_ACT * 8) / 256)            // N*32 floats / 4 per thread / 256
#define BN_EPS  1e-5f
#define XS      20                             // smem stride (floats) per cin

// ---------------- scratch (no allocations allowed) ----------------
__device__ float g_h1[(size_t)N_ACT * 32];     // conv1 raw output
__device__ float g_h2[(size_t)N_ACT * 32];     // conv2 raw output
__device__ float g_part1[NB_CONV * 64];        // per-block [sum(32), sumsq(32)]
__device__ float g_part2[NB_CONV * 64];
__device__ float g_coef1[64];                  // [a(32), c(32)] : y = a*h + c
__device__ float g_coef2[64];

// ---------------- f32x2 helpers (Blackwell packed fp32) ----------------
__device__ __forceinline__ unsigned long long splat2(float w) {
    unsigned long long r;
    asm("mov.b64 %0, {%1, %1};" : "=l"(r) : "f"(w));
    return r;
}
__device__ __forceinline__ float2 unpack2(unsigned long long v) {
    float2 f;
    asm("mov.b64 {%0, %1}, %2;" : "=f"(f.x), "=f"(f.y) : "l"(v));
    return f;
}
__device__ __forceinline__ void fma2(unsigned long long& acc,
                                     unsigned long long x,
                                     unsigned long long w) {
    asm("fma.rn.f32x2 %0, %1, %2, %0;" : "+l"(acc) : "l"(x), "l"(w));
}

// ---------------- conv: H[i] = sum_k gather(X, idx[k]) @ W[k] ----------------
// Warp tile: 16 rows x 32 cout. lane = cout in compute; lane = cin in gather.
// WHICH==0: X = Xin raw,              H = g_h1, part = g_part1
// WHICH==1: X = bn1relu(g_h1) inline, H = g_h2, part = g_part2
template<int WHICH>
__global__ __launch_bounds__(256, 4) void conv_kernel(
    const float* __restrict__ Xin, const int* __restrict__ IDX,
    const float* __restrict__ Wg)
{
    const float* X    = WHICH ? g_h1    : Xin;
    float*       H    = WHICH ? g_h2    : g_h1;
    float*       part = WHICH ? g_part2 : g_part1;

    // per-warp transposed tile: [cin][row], stride XS=20 floats (80B, 16B aligned)
    __shared__ __align__(16) float sX[8 * 32 * XS];
    __shared__ float red[2][8][32];

    const int tid   = threadIdx.x;
    const int warp  = tid >> 5;
    const int lane  = tid & 31;
    const int wbase = blockIdx.x * ROWS_PB + warp * 16;
    float* xw = sX + warp * 32 * XS;

    // bn1+relu coefs for the fused gather transform (lane == channel)
    float a_bn = 0.f, c_bn = 0.f;
    if (WHICH) { a_bn = g_coef1[lane]; c_bn = g_coef1[32 + lane]; }

    unsigned long long acc[8];
#pragma unroll
    for (int i = 0; i < 8; i++) acc[i] = 0ULL;

    // idx row for this lane (lanes 16-31 duplicate 0-15); clamp keeps tail legal
    const int rowc = min(wbase + (lane & 15), N_ACT - 1);

#pragma unroll 1
    for (int k = 0; k < 8; k++) {
        // ---- cooperative coalesced gather: row r -> all lanes read 128B together
        const int myj = IDX[(size_t)k * N_ACT + rowc];
        float vals[16];
#pragma unroll
        for (int r = 0; r < 16; r++) {
            int j = __shfl_sync(0xffffffffu, myj, r);   // warp-uniform
            float t = 0.f;
            if (j < N_ACT) {
                t = X[(size_t)j * 32 + lane];
                if (WHICH) t = fmaxf(fmaf(t, a_bn, c_bn), 0.f);
            }
            vals[r] = t;
        }
        __syncwarp();   // compute of previous k done reading xw
        // lane(=cin) writes its column: 4x STS.128, conflict-free (banks 0..31 once)
#pragma unroll
        for (int q = 0; q < 4; q++) {
            float4 v = make_float4(vals[4 * q], vals[4 * q + 1],
                                   vals[4 * q + 2], vals[4 * q + 3]);
            *(float4*)(xw + lane * XS + 4 * q) = v;
        }
        __syncwarp();

        // ---- compute: per cin -> 1 LDG.32 (W, L1-hot) + 4 LDS.128 bcast + 8 fma2
#pragma unroll
        for (int cin = 0; cin < 32; cin++) {
            unsigned long long ws = splat2(Wg[k * 1024 + cin * 32 + lane]);
            const ulonglong2* xp = (const ulonglong2*)(xw + cin * XS);
#pragma unroll
            for (int q = 0; q < 4; q++) {
                ulonglong2 t = xp[q];
                fma2(acc[2 * q],     t.x, ws);
                fma2(acc[2 * q + 1], t.y, ws);
            }
        }
    }

    // ---- BN stat partials (from registers) ----
    const int valid = N_ACT - wbase;   // may be <=0 for dead tail warps
    float s = 0.f, sq = 0.f;
#pragma unroll
    for (int m = 0; m < 8; m++) {
        float2 f = unpack2(acc[m]);
        if (2 * m     < valid) { s += f.x; sq += f.x * f.x; }
        if (2 * m + 1 < valid) { s += f.y; sq += f.y * f.y; }
    }
    red[0][warp][lane] = s;
    red[1][warp][lane] = sq;

    // ---- store H (coalesced: warp writes 128B per row) ----
#pragma unroll
    for (int m = 0; m < 8; m++) {
        float2 f = unpack2(acc[m]);
        int r0 = wbase + 2 * m;
        if (r0     < N_ACT) H[(size_t)r0 * 32 + lane]       = f.x;
        if (r0 + 1 < N_ACT) H[(size_t)(r0 + 1) * 32 + lane] = f.y;
    }

    __syncthreads();
    if (warp == 0) {
        float ts = 0.f, tq = 0.f;
#pragma unroll
        for (int w = 0; w < 8; w++) { ts += red[0][w][lane]; tq += red[1][w][lane]; }
        part[blockIdx.x * 64 + lane]      = ts;
        part[blockIdx.x * 64 + 32 + lane] = tq;
    }
}

// ---------------- reduce partials -> affine coefs a, c ----------------
__global__ void reduce_kernel(const float* __restrict__ gamma,
                              const float* __restrict__ beta, int which)
{
    const float* part = which ? g_part2 : g_part1;
    float*       coef = which ? g_coef2 : g_coef1;

    const int c = threadIdx.x & 31;
    const int s = threadIdx.x >> 5;   // 32 slices, 1024 threads
    float s1 = 0.f, s2 = 0.f;
    for (int b = s; b < NB_CONV; b += 32) {
        s1 += part[b * 64 + c];
        s2 += part[b * 64 + 32 + c];
    }
    __shared__ float sh1[32][33], sh2[32][33];
    sh1[c][s] = s1;
    sh2[c][s] = s2;
    __syncthreads();
    if (s == 0) {
        float sum = 0.f, sq = 0.f;
#pragma unroll
        for (int i = 0; i < 32; i++) { sum += sh1[c][i]; sq += sh2[c][i]; }
        float mean = sum / (float)N_ACT;
        float var  = fmaxf(sq / (float)N_ACT - mean * mean, 0.f);
        float a    = gamma[c] * rsqrtf(var + BN_EPS);
        coef[c]      = a;
        coef[32 + c] = beta[c] - mean * a;
    }
}

// ---------------- bn2 + residual add -> out ----------------
__global__ void final_kernel(const float* __restrict__ X, float* __restrict__ O)
{
    int i4 = blockIdx.x * 256 + threadIdx.x;
    int cb = i4 & 7;
    float4 a = ((const float4*)g_coef2)[cb];
    float4 c = ((const float4*)g_coef2)[8 + cb];
    float4 v = ((const float4*)g_h2)[i4];
    float4 x = ((const float4*)X)[i4];
    float4 o;
    o.x = fmaf(v.x, a.x, c.x) + x.x;
    o.y = fmaf(v.y, a.y, c.y) + x.y;
    o.z = fmaf(v.z, a.z, c.z) + x.z;
    o.w = fmaf(v.w, a.w, c.w) + x.w;
    ((float4*)O)[i4] = o;
}

extern "C" void kernel_launch(void* const* d_in, const int* in_sizes, int n_in,
                              void* d_out, int out_size)
{
    const float* x   = (const float*)d_in[0];
    const int*   idx = (const int*)  d_in[1];
    const float* W1  = (const float*)d_in[2];
    const float* g1  = (const float*)d_in[3];
    const float* b1  = (const float*)d_in[4];
    const float* W2  = (const float*)d_in[5];
    const float* g2  = (const float*)d_in[6];
    const float* b2  = (const float*)d_in[7];
    float* out = (float*)d_out;

    conv_kernel<0><<<NB_CONV, 256>>>(x, idx, W1);     // h1 = conv1(x), partials1
    reduce_kernel <<<1, 1024>>>(g1, b1, 0);           // coef1
    conv_kernel<1><<<NB_CONV, 256>>>(x, idx, W2);     // h2 = conv2(bn1relu(h1)), partials2
    reduce_kernel <<<1, 1024>>>(g2, b2, 1);           // coef2
    final_kernel  <<<NB_ELT, 256>>>(x, out);          // out = bn2(h2) + x
}

// round 5
// speedup vs baseline: 1.0075x; 1.0075x over previous
#include <cuda_runtime.h>
#include <cstdint>

#define N_ACT   1500000
#define ROWS_PB 128                                 // 8 warps x 16 rows
#define NB_CONV ((N_ACT + ROWS_PB - 1) / ROWS_PB)   // 11719 blocks
#define NB_ELT  ((N_ACT * 8) / 256)                 // N*32 floats / 4 per thread / 256
#define BN_EPS  1e-5f
#define XS      20                                  // smem stride (floats) per cin

// ---------------- scratch (no allocations allowed) ----------------
__device__ float g_h1[(size_t)N_ACT * 32];     // conv1 raw output
__device__ float g_h2[(size_t)N_ACT * 32];     // conv2 raw output
__device__ float g_part1[64 * NB_CONV];        // transposed: [stat][block]
__device__ float g_part2[64 * NB_CONV];
__device__ float g_stat1[64];                  // summed stats [sum(32), sumsq(32)]
__device__ float g_stat2[64];
__device__ float g_coef1[64];                  // [a(32), c(32)] : y = a*h + c
__device__ float g_coef2[64];

// ---------------- f32x2 helpers (Blackwell packed fp32) ----------------
__device__ __forceinline__ unsigned long long splat2(float w) {
    unsigned long long r;
    asm("mov.b64 %0, {%1, %1};" : "=l"(r) : "f"(w));
    return r;
}
__device__ __forceinline__ float2 unpack2(unsigned long long v) {
    float2 f;
    asm("mov.b64 {%0, %1}, %2;" : "=f"(f.x), "=f"(f.y) : "l"(v));
    return f;
}
__device__ __forceinline__ void fma2(unsigned long long& acc,
                                     unsigned long long x,
                                     unsigned long long w) {
    asm("fma.rn.f32x2 %0, %1, %2, %0;" : "+l"(acc) : "l"(x), "l"(w));
}

// ---------------- conv: H[i] = sum_k gather(X, idx[k]) @ W[k] ----------------
// Warp tile: 16 rows x 32 cout. lane = cout in compute; lane = cin in gather.
// Software pipeline: idx prefetched 2 iters ahead, gathered rows 1 iter ahead.
template<int WHICH>
__global__ __launch_bounds__(256, 4) void conv_kernel(
    const float* __restrict__ Xin, const int* __restrict__ IDX,
    const float* __restrict__ Wg)
{
    const float* X    = WHICH ? g_h1    : Xin;
    float*       H    = WHICH ? g_h2    : g_h1;
    float*       part = WHICH ? g_part2 : g_part1;

    // per-warp transposed tile: [cin][row], stride XS=20 floats (80B, 16B aligned)
    __shared__ __align__(16) float sX[8 * 32 * XS];
    __shared__ float red[2][8][32];

    const int tid   = threadIdx.x;
    const int warp  = tid >> 5;
    const int lane  = tid & 31;
    const int wbase = blockIdx.x * ROWS_PB + warp * 16;
    float* xw = sX + warp * 32 * XS;

    // bn1+relu coefs for the fused gather transform (lane == channel)
    float a_bn = 0.f, c_bn = 0.f;
    if (WHICH) { a_bn = g_coef1[lane]; c_bn = g_coef1[32 + lane]; }

    unsigned long long acc[8];
#pragma unroll
    for (int i = 0; i < 8; i++) acc[i] = 0ULL;

    // idx row for this lane (lanes 16-31 duplicate 0-15); clamp keeps tail legal
    const int rowc = min(wbase + (lane & 15), N_ACT - 1);

    float vals[16];
    // ---- prologue: gather k=0 (only place full latency is exposed) ----
    int myj_cur = IDX[rowc];
#pragma unroll
    for (int r = 0; r < 16; r++) {
        int j = __shfl_sync(0xffffffffu, myj_cur, r);
        float t = 0.f;
        if (j < N_ACT) {
            t = X[(size_t)j * 32 + lane];
            if (WHICH) t = fmaxf(fmaf(t, a_bn, c_bn), 0.f);
        }
        vals[r] = t;
    }
    int myj_nxt = IDX[(size_t)N_ACT + rowc];   // idx for k=1, lands during k=0 compute

#pragma unroll 1
    for (int k = 0; k < 8; k++) {
        __syncwarp();   // compute of previous k done reading xw
        // lane(=cin) writes its column: 4x STS.128, conflict-free (banks 0..31 once)
#pragma unroll
        for (int q = 0; q < 4; q++) {
            float4 v = make_float4(vals[4 * q], vals[4 * q + 1],
                                   vals[4 * q + 2], vals[4 * q + 3]);
            *(float4*)(xw + lane * XS + 4 * q) = v;
        }
        __syncwarp();

        // ---- prefetch gather for k+1: LDGs fly while compute(k) runs ----
        if (k < 7) {
            int myj = myj_cur = myj_nxt;               // loaded 1 iter ago: ready
            if (k < 6) myj_nxt = IDX[(size_t)(k + 2) * N_ACT + rowc];
#pragma unroll
            for (int r = 0; r < 16; r++) {
                int j = __shfl_sync(0xffffffffu, myj, r);
                float t = 0.f;
                if (j < N_ACT) {
                    t = X[(size_t)j * 32 + lane];
                    if (WHICH) t = fmaxf(fmaf(t, a_bn, c_bn), 0.f);
                }
                vals[r] = t;
            }
        }

        // ---- compute: per cin -> 1 LDG.32 (W, L1-hot) + 4 LDS.128 bcast + 8 fma2
        const float* wk = Wg + k * 1024;
#pragma unroll
        for (int cin = 0; cin < 32; cin++) {
            unsigned long long ws = splat2(wk[cin * 32 + lane]);
            const ulonglong2* xp = (const ulonglong2*)(xw + cin * XS);
#pragma unroll
            for (int q = 0; q < 4; q++) {
                ulonglong2 t = xp[q];
                fma2(acc[2 * q],     t.x, ws);
                fma2(acc[2 * q + 1], t.y, ws);
            }
        }
    }

    // ---- BN stat partials (from registers) ----
    const int valid = N_ACT - wbase;   // may be <=0 for dead tail warps
    float s = 0.f, sq = 0.f;
#pragma unroll
    for (int m = 0; m < 8; m++) {
        float2 f = unpack2(acc[m]);
        if (2 * m     < valid) { s += f.x; sq += f.x * f.x; }
        if (2 * m + 1 < valid) { s += f.y; sq += f.y * f.y; }
    }
    red[0][warp][lane] = s;
    red[1][warp][lane] = sq;

    // ---- store H (coalesced: warp writes 128B per row) ----
#pragma unroll
    for (int m = 0; m < 8; m++) {
        float2 f = unpack2(acc[m]);
        int r0 = wbase + 2 * m;
        if (r0     < N_ACT) H[(size_t)r0 * 32 + lane]       = f.x;
        if (r0 + 1 < N_ACT) H[(size_t)(r0 + 1) * 32 + lane] = f.y;
    }

    __syncthreads();
    if (warp == 0) {
        float ts = 0.f, tq = 0.f;
#pragma unroll
        for (int w = 0; w < 8; w++) { ts += red[0][w][lane]; tq += red[1][w][lane]; }
        // transposed store: [stat][block] so reduce_kernel reads coalesced
        part[(size_t)lane        * NB_CONV + blockIdx.x] = ts;
        part[(size_t)(32 + lane) * NB_CONV + blockIdx.x] = tq;
    }
}

// ---------------- reduce: 64 blocks, block c sums its stat row (coalesced) ----
__global__ void reduce_kernel(int which)
{
    const float* part = which ? g_part2 : g_part1;
    float*       stat = which ? g_stat2 : g_stat1;

    const float* row = part + (size_t)blockIdx.x * NB_CONV;
    float s = 0.f;
#pragma unroll 4
    for (int i = threadIdx.x; i < NB_CONV; i += 256) s += row[i];

    __shared__ float sh[256];
    sh[threadIdx.x] = s;
    __syncthreads();
#pragma unroll
    for (int o = 128; o > 0; o >>= 1) {
        if (threadIdx.x < o) sh[threadIdx.x] += sh[threadIdx.x + o];
        __syncthreads();
    }
    if (threadIdx.x == 0) stat[blockIdx.x] = sh[0];
}

// ---------------- coefs: a = g*rsqrt(var+eps), c = b - mean*a ----------------
__global__ void coef_kernel(const float* __restrict__ gamma,
                            const float* __restrict__ beta, int which)
{
    const float* stat = which ? g_stat2 : g_stat1;
    float*       coef = which ? g_coef2 : g_coef1;
    int c = threadIdx.x;   // 32 threads
    float mean = stat[c] / (float)N_ACT;
    float var  = fmaxf(stat[32 + c] / (float)N_ACT - mean * mean, 0.f);
    float a    = gamma[c] * rsqrtf(var + BN_EPS);
    coef[c]      = a;
    coef[32 + c] = beta[c] - mean * a;
}

// ---------------- bn2 + residual add -> out ----------------
__global__ void final_kernel(const float* __restrict__ X, float* __restrict__ O)
{
    int i4 = blockIdx.x * 256 + threadIdx.x;
    int cb = i4 & 7;
    float4 a = ((const float4*)g_coef2)[cb];
    float4 c = ((const float4*)g_coef2)[8 + cb];
    float4 v = ((const float4*)g_h2)[i4];
    float4 x = ((const float4*)X)[i4];
    float4 o;
    o.x = fmaf(v.x, a.x, c.x) + x.x;
    o.y = fmaf(v.y, a.y, c.y) + x.y;
    o.z = fmaf(v.z, a.z, c.z) + x.z;
    o.w = fmaf(v.w, a.w, c.w) + x.w;
    ((float4*)O)[i4] = o;
}

extern "C" void kernel_launch(void* const* d_in, const int* in_sizes, int n_in,
                              void* d_out, int out_size)
{
    const float* x   = (const float*)d_in[0];
    const int*   idx = (const int*)  d_in[1];
    const float* W1  = (const float*)d_in[2];
    const float* g1  = (const float*)d_in[3];
    const float* b1  = (const float*)d_in[4];
    const float* W2  = (const float*)d_in[5];
    const float* g2  = (const float*)d_in[6];
    const float* b2  = (const float*)d_in[7];
    float* out = (float*)d_out;

    conv_kernel<0><<<NB_CONV, 256>>>(x, idx, W1);   // h1 = conv1(x), partials1
    reduce_kernel <<<64, 256>>>(0);                 // stat1
    coef_kernel   <<<1, 32>>>(g1, b1, 0);           // coef1
    conv_kernel<1><<<NB_CONV, 256>>>(x, idx, W2);   // h2 = conv2(bn1relu(h1)), partials2
    reduce_kernel <<<64, 256>>>(1);                 // stat2
    coef_kernel   <<<1, 32>>>(g2, b2, 1);           // coef2
    final_kernel  <<<NB_ELT, 256>>>(x, out);        // out = bn2(h2) + x
}